// round 2
// baseline (speedup 1.0000x reference)
#include <cuda_runtime.h>
#include <math.h>

#define DIM    1024
#define BATCH  2
#define TLEN   2048
#define HEADS  16
#define HD     64
#define ROWS   (BATCH*TLEN)          // 4096
#define HROWS  (BATCH*HEADS*TLEN)    // 65536
#define THRESH 0.29514f
#define SHARP  15.0f

// ---------------- scratch (device globals: no allocations allowed) ----------
__device__ float d_xnorm[ROWS*DIM];
__device__ float d_Q[HROWS*HD];
__device__ float d_K[HROWS*HD];
__device__ float d_V[HROWS*HD];
__device__ float d_gq[HROWS];
__device__ float d_coll[ROWS*DIM];

// ---------------- LayerNorm: one block per row --------------------------------
__global__ void ln_kernel(const float* __restrict__ x,
                          const float* __restrict__ w,
                          const float* __restrict__ bvec) {
    int row = blockIdx.x;
    int tid = threadIdx.x;
    float4 v = ((const float4*)(x + (size_t)row*DIM))[tid];
    float s  = v.x + v.y + v.z + v.w;
    float ss = v.x*v.x + v.y*v.y + v.z*v.z + v.w*v.w;
    #pragma unroll
    for (int o = 16; o > 0; o >>= 1) {
        s  += __shfl_xor_sync(0xffffffffu, s,  o);
        ss += __shfl_xor_sync(0xffffffffu, ss, o);
    }
    __shared__ float rs[8], rss[8];
    int wid = tid >> 5, lane = tid & 31;
    if (lane == 0) { rs[wid] = s; rss[wid] = ss; }
    __syncthreads();
    s = 0.f; ss = 0.f;
    #pragma unroll
    for (int i = 0; i < 8; i++) { s += rs[i]; ss += rss[i]; }
    float mean = s * (1.0f/DIM);
    float var  = ss * (1.0f/DIM) - mean*mean;
    float rstd = rsqrtf(var + 1e-5f);
    float4 wv = ((const float4*)w)[tid];
    float4 bv = ((const float4*)bvec)[tid];
    float4 o;
    o.x = (v.x-mean)*rstd*wv.x + bv.x;
    o.y = (v.y-mean)*rstd*wv.y + bv.y;
    o.z = (v.z-mean)*rstd*wv.z + bv.z;
    o.w = (v.w-mean)*rstd*wv.w + bv.w;
    ((float4*)(d_xnorm + (size_t)row*DIM))[tid] = o;
}

// ---------------- 128x128x8 SGEMM for Q/K/V projections -----------------------
// z=0: xnorm@Wq -> Q(head-major), z=1: xnorm@Wk -> K, z=2: x@Wv -> V
__global__ __launch_bounds__(256)
void gemm_qkv_kernel(const float* __restrict__ x,
                     const float* __restrict__ Wq,
                     const float* __restrict__ Wk,
                     const float* __restrict__ Wv) {
    __shared__ float As[8][132];
    __shared__ float Bs[8][132];
    int z = blockIdx.z;
    const float* A = (z == 2) ? x : d_xnorm;
    const float* W = (z == 0) ? Wq : (z == 1) ? Wk : Wv;
    float* dst = (z == 0) ? d_Q : (z == 1) ? d_K : d_V;

    int tid = threadIdx.x;
    int tx = tid & 15, ty = tid >> 4;
    int m0 = blockIdx.y * 128, n0 = blockIdx.x * 128;

    float acc[8][8];
    #pragma unroll
    for (int i = 0; i < 8; i++)
        #pragma unroll
        for (int j = 0; j < 8; j++) acc[i][j] = 0.f;

    int ar = tid >> 1, ac = (tid & 1) * 4;     // A tile: 128 rows x 8 cols
    int br = tid >> 5, bc = (tid & 31) * 4;    // B tile: 8 rows x 128 cols
    const float* Aptr = A + (size_t)(m0 + ar)*DIM + ac;
    const float* Wptr = W + (size_t)br*DIM + n0 + bc;

    for (int k0 = 0; k0 < DIM; k0 += 8) {
        float4 av = *(const float4*)(Aptr + k0);
        float4 bv = *(const float4*)(Wptr + (size_t)k0*DIM);
        __syncthreads();
        As[ac+0][ar] = av.x; As[ac+1][ar] = av.y;
        As[ac+2][ar] = av.z; As[ac+3][ar] = av.w;
        *(float4*)&Bs[br][bc] = bv;
        __syncthreads();
        #pragma unroll
        for (int kk = 0; kk < 8; kk++) {
            float4 a0 = *(const float4*)&As[kk][ty*8];
            float4 a1 = *(const float4*)&As[kk][ty*8+4];
            float4 b0 = *(const float4*)&Bs[kk][tx*8];
            float4 b1 = *(const float4*)&Bs[kk][tx*8+4];
            float a[8] = {a0.x,a0.y,a0.z,a0.w,a1.x,a1.y,a1.z,a1.w};
            float bb[8] = {b0.x,b0.y,b0.z,b0.w,b1.x,b1.y,b1.z,b1.w};
            #pragma unroll
            for (int i = 0; i < 8; i++)
                #pragma unroll
                for (int j = 0; j < 8; j++)
                    acc[i][j] = fmaf(a[i], bb[j], acc[i][j]);
        }
    }

    // store head-major: [b,h,t,d]
    #pragma unroll
    for (int i = 0; i < 8; i++) {
        int m = m0 + ty*8 + i;
        int b = m >> 11, t = m & 2047;
        #pragma unroll
        for (int j = 0; j < 8; j++) {
            int n = n0 + tx*8 + j;
            int h = n >> 6, dd = n & 63;
            dst[(((size_t)(b*HEADS + h))*TLEN + t)*HD + dd] = acc[i][j];
        }
    }
}

// ---------------- per-head L2 normalize + gates, fold gate_k into V -----------
__global__ void normgate_kernel(const float* __restrict__ gqv,
                                const float* __restrict__ gkv) {
    int r = (blockIdx.x * blockDim.x + threadIdx.x) >> 5;
    int lane = threadIdx.x & 31;
    if (r >= HROWS) return;
    float* q = d_Q + (size_t)r*HD;
    float* k = d_K + (size_t)r*HD;
    float* v = d_V + (size_t)r*HD;

    float q0 = q[lane], q1 = q[lane+32];
    float ss = q0*q0 + q1*q1;
    #pragma unroll
    for (int o = 16; o > 0; o >>= 1) ss += __shfl_xor_sync(0xffffffffu, ss, o);
    float inv = 1.0f / fmaxf(sqrtf(ss), 1e-12f);
    q0 *= inv; q1 *= inv;
    q[lane] = q0; q[lane+32] = q1;
    float g = q0*gqv[lane] + q1*gqv[lane+32];
    #pragma unroll
    for (int o = 16; o > 0; o >>= 1) g += __shfl_xor_sync(0xffffffffu, g, o);
    if (lane == 0) d_gq[r] = g;

    float k0 = k[lane], k1 = k[lane+32];
    ss = k0*k0 + k1*k1;
    #pragma unroll
    for (int o = 16; o > 0; o >>= 1) ss += __shfl_xor_sync(0xffffffffu, ss, o);
    inv = 1.0f / fmaxf(sqrtf(ss), 1e-12f);
    k0 *= inv; k1 *= inv;
    k[lane] = k0; k[lane+32] = k1;
    float gk = k0*gkv[lane] + k1*gkv[lane+32];
    #pragma unroll
    for (int o = 16; o > 0; o >>= 1) gk += __shfl_xor_sync(0xffffffffu, gk, o);
    v[lane]    *= gk;
    v[lane+32] *= gk;
}

// ---------------- fused attention: 64t x 64s tiles, P in smem -----------------
// collapse[t,:] = gq[t] * sum_s sigmoid((q_t . k_s - TH)*SHARP) * (gk_s * v_s)
__global__ __launch_bounds__(128)
void attn_kernel() {
    extern __shared__ float sm[];
    float* Qs = sm;              // [d][t]  64 x 68
    float* Ks = sm + 64*68;      // [d][s]
    float* Vs = sm + 2*64*68;    // [s][d]
    float* Ps = sm + 3*64*68;    // [s][t]
    __shared__ float gqs[64];

    int tid = threadIdx.x;
    int h = blockIdx.y, b = blockIdx.z;
    int t0 = blockIdx.x * 64;
    size_t base = (size_t)(b*HEADS + h)*TLEN;
    const float* Qg = d_Q + (base + t0)*HD;
    const float* Kb = d_K + base*HD;
    const float* Vb = d_V + base*HD;

    for (int e = tid; e < 4096; e += 128) {
        int t = e >> 6, dd = e & 63;
        Qs[dd*68 + t] = Qg[e];
    }
    if (tid < 64) gqs[tid] = d_gq[base + t0 + tid];

    int tx = tid & 15, ty = tid >> 4;   // tx: 16 cols of 4, ty: 8 rows of 8
    float acc[8][4];
    #pragma unroll
    for (int i = 0; i < 8; i++)
        #pragma unroll
        for (int j = 0; j < 4; j++) acc[i][j] = 0.f;

    for (int s0 = 0; s0 < TLEN; s0 += 64) {
        __syncthreads();   // prior P.V reads of Ps/Vs done before overwrite
        const float* Kg = Kb + (size_t)s0*HD;
        const float* Vg = Vb + (size_t)s0*HD;
        for (int e = tid; e < 4096; e += 128) {
            int s = e >> 6, dd = e & 63;
            Ks[dd*68 + s] = Kg[e];
            Vs[s*68 + dd] = Vg[e];
        }
        __syncthreads();

        // P = sigmoid((Q.K^T - TH)*SHARP)
        float p[8][4];
        #pragma unroll
        for (int i = 0; i < 8; i++)
            #pragma unroll
            for (int j = 0; j < 4; j++) p[i][j] = 0.f;
        #pragma unroll 8
        for (int kk = 0; kk < 64; kk++) {
            float4 a0 = *(const float4*)&Qs[kk*68 + ty*8];
            float4 a1 = *(const float4*)&Qs[kk*68 + ty*8 + 4];
            float4 bv = *(const float4*)&Ks[kk*68 + tx*4];
            float a[8] = {a0.x,a0.y,a0.z,a0.w,a1.x,a1.y,a1.z,a1.w};
            float bb[4] = {bv.x,bv.y,bv.z,bv.w};
            #pragma unroll
            for (int i = 0; i < 8; i++)
                #pragma unroll
                for (int j = 0; j < 4; j++)
                    p[i][j] = fmaf(a[i], bb[j], p[i][j]);
        }
        #pragma unroll
        for (int i = 0; i < 8; i++)
            #pragma unroll
            for (int j = 0; j < 4; j++) {
                float zv = (p[i][j] - THRESH) * SHARP;
                float r = 1.0f / (1.0f + __expf(-zv));
                Ps[(tx*4 + j)*68 + ty*8 + i] = r;
            }
        __syncthreads();

        // acc += P @ V'
        #pragma unroll 8
        for (int ssi = 0; ssi < 64; ssi++) {
            float4 a0 = *(const float4*)&Ps[ssi*68 + ty*8];
            float4 a1 = *(const float4*)&Ps[ssi*68 + ty*8 + 4];
            float4 vv = *(const float4*)&Vs[ssi*68 + tx*4];
            float a[8] = {a0.x,a0.y,a0.z,a0.w,a1.x,a1.y,a1.z,a1.w};
            float bb[4] = {vv.x,vv.y,vv.z,vv.w};
            #pragma unroll
            for (int i = 0; i < 8; i++)
                #pragma unroll
                for (int j = 0; j < 4; j++)
                    acc[i][j] = fmaf(a[i], bb[j], acc[i][j]);
        }
    }

    // epilogue: * gate_q, scatter back to [B,T,D]
    float* Cb = d_coll + ((size_t)(b*TLEN) + t0)*DIM + h*HD;
    #pragma unroll
    for (int i = 0; i < 8; i++) {
        int t = ty*8 + i;
        float gm = gqs[t];
        #pragma unroll
        for (int j = 0; j < 4; j++)
            Cb[(size_t)t*DIM + tx*4 + j] = acc[i][j] * gm;
    }
}

// ---------------- output GEMM: collapse @ Wo + bo -----------------------------
__global__ __launch_bounds__(256)
void gemm_out_kernel(const float* __restrict__ W,
                     const float* __restrict__ bo,
                     float* __restrict__ out) {
    __shared__ float As[8][132];
    __shared__ float Bs[8][132];
    int tid = threadIdx.x;
    int tx = tid & 15, ty = tid >> 4;
    int m0 = blockIdx.y * 128, n0 = blockIdx.x * 128;

    float acc[8][8];
    #pragma unroll
    for (int i = 0; i < 8; i++)
        #pragma unroll
        for (int j = 0; j < 8; j++) acc[i][j] = 0.f;

    int ar = tid >> 1, ac = (tid & 1) * 4;
    int br = tid >> 5, bc = (tid & 31) * 4;
    const float* Aptr = d_coll + (size_t)(m0 + ar)*DIM + ac;
    const float* Wptr = W + (size_t)br*DIM + n0 + bc;

    for (int k0 = 0; k0 < DIM; k0 += 8) {
        float4 av = *(const float4*)(Aptr + k0);
        float4 bv = *(const float4*)(Wptr + (size_t)k0*DIM);
        __syncthreads();
        As[ac+0][ar] = av.x; As[ac+1][ar] = av.y;
        As[ac+2][ar] = av.z; As[ac+3][ar] = av.w;
        *(float4*)&Bs[br][bc] = bv;
        __syncthreads();
        #pragma unroll
        for (int kk = 0; kk < 8; kk++) {
            float4 a0 = *(const float4*)&As[kk][ty*8];
            float4 a1 = *(const float4*)&As[kk][ty*8+4];
            float4 b0 = *(const float4*)&Bs[kk][tx*8];
            float4 b1 = *(const float4*)&Bs[kk][tx*8+4];
            float a[8] = {a0.x,a0.y,a0.z,a0.w,a1.x,a1.y,a1.z,a1.w};
            float bb[8] = {b0.x,b0.y,b0.z,b0.w,b1.x,b1.y,b1.z,b1.w};
            #pragma unroll
            for (int i = 0; i < 8; i++)
                #pragma unroll
                for (int j = 0; j < 8; j++)
                    acc[i][j] = fmaf(a[i], bb[j], acc[i][j]);
        }
    }

    #pragma unroll
    for (int i = 0; i < 8; i++) {
        int m = m0 + ty*8 + i;
        #pragma unroll
        for (int j = 0; j < 8; j++) {
            int n = n0 + tx*8 + j;
            out[(size_t)m*DIM + n] = acc[i][j] + bo[n];
        }
    }
}

// ---------------- launch ------------------------------------------------------
extern "C" void kernel_launch(void* const* d_in, const int* in_sizes, int n_in,
                              void* d_out, int out_size) {
    const float* x   = (const float*)d_in[0];
    const float* Wq  = (const float*)d_in[1];
    const float* Wk  = (const float*)d_in[2];
    const float* Wv  = (const float*)d_in[3];
    const float* gqv = (const float*)d_in[4];
    const float* gkv = (const float*)d_in[5];
    const float* Wo  = (const float*)d_in[6];
    const float* bo  = (const float*)d_in[7];
    const float* lnw = (const float*)d_in[8];
    const float* lnb = (const float*)d_in[9];
    float* out = (float*)d_out;

    const int attn_smem = 4*64*68*4;  // 69632 B
    cudaFuncSetAttribute(attn_kernel,
                         cudaFuncAttributeMaxDynamicSharedMemorySize, attn_smem);

    ln_kernel<<<ROWS, 256>>>(x, lnw, lnb);
    gemm_qkv_kernel<<<dim3(8, 32, 3), 256>>>(x, Wq, Wk, Wv);
    normgate_kernel<<<HROWS*32/256, 256>>>(gqv, gkv);
    attn_kernel<<<dim3(TLEN/64, HEADS, BATCH), 128, attn_smem>>>();
    gemm_out_kernel<<<dim3(8, 32), 256>>>(Wo, bo, out);
}